// round 16
// baseline (speedup 1.0000x reference)
#include <cuda_runtime.h>
#include <cuda_bf16.h>
#include <cuda_fp16.h>
#include <math.h>
#include <stdint.h>

// ============================================================================
// CrossAttentionReader — GB300 sm_103a, round 16
//  - base: round-15 (165.3us)
//  - post-join pipelined: rows split in half, attn overlaps gemm2/ln
//  - rowstat: 2 rows/warp (2x MLP)
//  - Wk/Wv/Wo converts batched into one launch
// ============================================================================

#define D_MAX     1024
#define M_MAX     32768
#define ROWS_MAX  2048
#define TKK       32
#define NHEADS    16

// ---- scratch (device globals; no allocation allowed) ----
__device__ float g_r[M_MAX];
__device__ float g_wbar[D_MAX];
__device__ float g_colpart[32 * D_MAX];
__device__ int   g_posidx[TKK];
__device__ int   g_negidx[TKK];
__device__ int   g_sign[ROWS_MAX];
__device__ unsigned long long g_cand[2 * 1024];
__device__ __half g_gk[64 * D_MAX];
__device__ __half g_gv[64 * D_MAX];
__device__ float g_KVk[64 * D_MAX];          // rows 0-31: Kp, 32-63: Kn
__device__ float g_KVv[64 * D_MAX];          // rows 0-31: Vp, 32-63: Vn
__device__ float g_qfull[(size_t)ROWS_MAX * D_MAX];
__device__ __half g_xh[(size_t)ROWS_MAX * D_MAX];
__device__ __half g_ch[(size_t)ROWS_MAX * D_MAX];
__device__ __half g_Wqh[(size_t)D_MAX * D_MAX];
__device__ __half g_Woh[(size_t)D_MAX * D_MAX];
__device__ __half g_Wkh[(size_t)D_MAX * D_MAX];
__device__ __half g_Wvh[(size_t)D_MAX * D_MAX];

// ============================ helpers ===================================
__device__ __forceinline__ uint32_t smem_u32(const void* p) {
    uint32_t a;
    asm("{ .reg .u64 t; cvta.to.shared.u64 t, %1; cvt.u32.u64 %0, t; }" : "=r"(a) : "l"(p));
    return a;
}
__device__ __forceinline__ void ldsm_x4(uint32_t* r, uint32_t addr) {
    asm volatile("ldmatrix.sync.aligned.m8n8.x4.shared.b16 {%0,%1,%2,%3}, [%4];"
                 : "=r"(r[0]), "=r"(r[1]), "=r"(r[2]), "=r"(r[3]) : "r"(addr));
}
__device__ __forceinline__ void mma_f16(float* d, const uint32_t* a, const uint32_t* b) {
    asm volatile("mma.sync.aligned.m16n8k16.row.col.f32.f16.f16.f32 "
                 "{%0,%1,%2,%3}, {%4,%5,%6,%7}, {%8,%9}, {%0,%1,%2,%3};"
                 : "+f"(d[0]), "+f"(d[1]), "+f"(d[2]), "+f"(d[3])
                 : "r"(a[0]), "r"(a[1]), "r"(a[2]), "r"(a[3]), "r"(b[0]), "r"(b[1]));
}
#define CP_ASYNC16(sa, gp) \
    asm volatile("cp.async.cg.shared.global [%0], [%1], 16;" :: "r"(sa), "l"(gp))
#define CP_COMMIT() asm volatile("cp.async.commit_group;" ::: "memory")
#define CP_WAIT(n)  asm volatile("cp.async.wait_group %0;" :: "n"(n) : "memory")

// warp bitonic: sort 32 u64 keys (one per lane) descending
__device__ __forceinline__ unsigned long long bsort32_desc(unsigned long long key, int lane) {
    #pragma unroll
    for (int k = 2; k <= 32; k <<= 1) {
        #pragma unroll
        for (int j = 16; j > 0; j >>= 1) {
            if (j >= k) continue;
            unsigned long long other = __shfl_xor_sync(0xffffffffu, key, j);
            bool keepMax = (((lane & j) == 0) == ((lane & k) == 0));
            bool gt = key > other;
            key = (keepMax == gt) ? key : other;
        }
    }
    return key;
}

__device__ __forceinline__ unsigned long long bmerge_top32(unsigned long long a,
                                                           unsigned long long b, int lane) {
    unsigned long long brev = __shfl_sync(0xffffffffu, b, 31 - lane);
    unsigned long long k = (a > brev) ? a : brev;
    #pragma unroll
    for (int j = 16; j > 0; j >>= 1) {
        unsigned long long other = __shfl_xor_sync(0xffffffffu, k, j);
        bool keepMax = ((lane & j) == 0);
        bool gt = k > other;
        k = (keepMax == gt) ? k : other;
    }
    return k;
}

// ---------------------------------------------------------------------------
// convert fp32 -> fp16 (single)
// ---------------------------------------------------------------------------
__global__ void cvt_kernel(const float* __restrict__ src, __half* __restrict__ dst, int n4) {
    int i = blockIdx.x * 256 + threadIdx.x;
    if (i >= n4) return;
    float4 v = ((const float4*)src)[i];
    __half2 a = __floats2half2_rn(v.x, v.y);
    __half2 b = __floats2half2_rn(v.z, v.w);
    ((__half2*)dst)[2 * i]     = a;
    ((__half2*)dst)[2 * i + 1] = b;
}

// batched convert of 3 weight matrices (grid.y selects)
__global__ void cvtW3_kernel(const float* __restrict__ Wk, const float* __restrict__ Wv,
                             const float* __restrict__ Wo,
                             __half* __restrict__ dk, __half* __restrict__ dv,
                             __half* __restrict__ dwo, int n4) {
    int i = blockIdx.x * 256 + threadIdx.x;
    if (i >= n4) return;
    const float* src = (blockIdx.y == 0) ? Wk : (blockIdx.y == 1) ? Wv : Wo;
    __half* dst      = (blockIdx.y == 0) ? dk : (blockIdx.y == 1) ? dv : dwo;
    float4 v = ((const float4*)src)[i];
    __half2 a = __floats2half2_rn(v.x, v.y);
    __half2 b = __floats2half2_rn(v.z, v.w);
    ((__half2*)dst)[2 * i]     = a;
    ((__half2*)dst)[2 * i + 1] = b;
}

// ---------------------------------------------------------------------------
// gather selected memory rows -> fp16 [64][1024]
// ---------------------------------------------------------------------------
__global__ void gather_kernel(const float* __restrict__ mk, const float* __restrict__ mv,
                              const int* __restrict__ pos, const int* __restrict__ neg,
                              __half* __restrict__ gk, __half* __restrict__ gv, int D) {
    int slot = blockIdx.x, mat = blockIdx.y;
    const float* src = mat ? mv : mk;
    __half* dst = mat ? gv : gk;
    int row = (slot < 32) ? pos[slot] : neg[slot - 32];
    const float* s = src + (size_t)row * D;
    __half* d = dst + (size_t)slot * D_MAX;
    int j = threadIdx.x * 4;
    float4 v = *(const float4*)(s + j);
    __half2 a = __floats2half2_rn(v.x, v.y);
    __half2 b = __floats2half2_rn(v.z, v.w);
    ((__half2*)d)[threadIdx.x * 2]     = a;
    ((__half2*)d)[threadIdx.x * 2 + 1] = b;
}

// ---------------------------------------------------------------------------
// column sum of Wq — two-stage deterministic reduction (32-way row split)
// ---------------------------------------------------------------------------
__global__ void colsum1_kernel(const float* __restrict__ W, float* __restrict__ part, int D) {
    int d = blockIdx.x * 256 + threadIdx.x;
    if (d >= D) return;
    int r0 = blockIdx.y * 32;
    float s = 0.f;
    for (int r = r0; r < r0 + 32; r++) s += W[(size_t)r * D + d];
    part[blockIdx.y * D + d] = s;
}
__global__ void colsum2_kernel(const float* __restrict__ part, float* __restrict__ wbar, int D) {
    int d = blockIdx.x * 256 + threadIdx.x;
    if (d >= D) return;
    float s = 0.f;
    #pragma unroll
    for (int i = 0; i < 32; i++) s += part[i * D + d];
    wbar[d] = s;
}

// ---------------------------------------------------------------------------
// per-row r[m] = sum / (sqrtD * norm) — 2 rows per warp for 2x MLP
// ---------------------------------------------------------------------------
__global__ void rowstat_kernel(const float* __restrict__ mk, float* __restrict__ r,
                               int M, int D, float sqrtD) {
    int warp = threadIdx.x >> 5, lane = threadIdx.x & 31;
    int m0 = blockIdx.x * 16 + warp * 2;
    if (m0 >= M) return;
    const float* row0 = mk + (size_t)m0 * D;
    const float* row1 = mk + (size_t)(m0 + 1) * D;
    float s0 = 0.f, q0 = 0.f, s1 = 0.f, q1 = 0.f;
    for (int j = lane * 4; j < D; j += 128) {
        float4 a = *(const float4*)(row0 + j);
        float4 b = *(const float4*)(row1 + j);
        s0 += a.x + a.y + a.z + a.w;
        q0 += a.x * a.x + a.y * a.y + a.z * a.z + a.w * a.w;
        s1 += b.x + b.y + b.z + b.w;
        q1 += b.x * b.x + b.y * b.y + b.z * b.z + b.w * b.w;
    }
    #pragma unroll
    for (int off = 16; off; off >>= 1) {
        s0 += __shfl_xor_sync(0xffffffffu, s0, off);
        q0 += __shfl_xor_sync(0xffffffffu, q0, off);
        s1 += __shfl_xor_sync(0xffffffffu, s1, off);
        q1 += __shfl_xor_sync(0xffffffffu, q1, off);
    }
    if (lane == 0) {
        r[m0]     = s0 / (sqrtD * sqrtf(q0));
        if (m0 + 1 < M) r[m0 + 1] = s1 / (sqrtD * sqrtf(q1));
    }
}

// ---------------------------------------------------------------------------
// sign(qm) per row
// ---------------------------------------------------------------------------
__global__ void qmsign_kernel(const float* __restrict__ x, const float* __restrict__ wbar,
                              int* __restrict__ sgn, int rows, int D) {
    int warp = threadIdx.x >> 5, lane = threadIdx.x & 31;
    int rn = blockIdx.x * 8 + warp;
    if (rn >= rows) return;
    const float* row = x + (size_t)rn * D;
    float s = 0.f;
    for (int j = lane * 4; j < D; j += 128) {
        float4 v = *(const float4*)(row + j);
        float4 w = *(const float4*)(wbar + j);
        s += v.x * w.x + v.y * w.y + v.z * w.z + v.w * w.w;
    }
    #pragma unroll
    for (int off = 16; off; off >>= 1) s += __shfl_xor_sync(0xffffffffu, s, off);
    if (lane == 0) sgn[rn] = (s >= 0.f) ? 1 : 0;
}

// ---------------------------------------------------------------------------
// topk: warp-register bitonic top-32
// ---------------------------------------------------------------------------
__global__ void topk_stage1(const float* __restrict__ r, int M,
                            unsigned long long* __restrict__ cand) {
    int mode = blockIdx.y, seg = blockIdx.x;
    int tid = threadIdx.x, warp = tid >> 5, lane = tid & 31;
    __shared__ unsigned long long wres[8][32];

    unsigned long long best = 0ull;
    #pragma unroll
    for (int c = 0; c < 4; c++) {
        int gi = seg * 1024 + warp * 128 + c * 32 + lane;
        unsigned long long key = 0ull;
        if (gi < M) {
            uint32_t b = __float_as_uint(r[gi]);
            uint32_t u = (b & 0x80000000u) ? ~b : (b | 0x80000000u);
            if (mode) u = ~u;
            key = ((unsigned long long)u << 32) | (uint32_t)(~gi);
        }
        key = bsort32_desc(key, lane);
        best = (c == 0) ? key : bmerge_top32(best, key, lane);
    }
    wres[warp][lane] = best;
    __syncthreads();
    if (warp == 0) {
        unsigned long long m01 = bmerge_top32(wres[0][lane], wres[1][lane], lane);
        unsigned long long m23 = bmerge_top32(wres[2][lane], wres[3][lane], lane);
        unsigned long long m45 = bmerge_top32(wres[4][lane], wres[5][lane], lane);
        unsigned long long m67 = bmerge_top32(wres[6][lane], wres[7][lane], lane);
        unsigned long long mA  = bmerge_top32(m01, m23, lane);
        unsigned long long mB  = bmerge_top32(m45, m67, lane);
        cand[mode * 1024 + seg * 32 + lane] = bmerge_top32(mA, mB, lane);
    }
}

__global__ void topk_stage2(const unsigned long long* __restrict__ cand, int nlists,
                            int* __restrict__ pos, int* __restrict__ neg) {
    int mode = blockIdx.x, lane = threadIdx.x;
    unsigned long long acc = cand[mode * 1024 + lane];
    for (int l = 1; l < nlists; l++)
        acc = bmerge_top32(acc, cand[mode * 1024 + l * 32 + lane], lane);
    int idx = (int)(~(uint32_t)(acc & 0xffffffffu));
    (mode ? neg : pos)[lane] = idx;
}

// ---------------------------------------------------------------------------
// proj GEMM (fp16 HMMA): C[64,1024] = gath[64,1024] @ W[1024,1024]^T
// ---------------------------------------------------------------------------
#define STR 80
#define POA 0
#define POB 5120
#define PBUFB 15360
#define PROJ_DSMEM (3 * PBUFB)

__global__ void __launch_bounds__(256) projgemm_kernel(
        const __half* __restrict__ gk, const __half* __restrict__ gv,
        const __half* __restrict__ Wkh, const __half* __restrict__ Wvh,
        float* __restrict__ KVk, float* __restrict__ KVv, int Kd) {
    extern __shared__ __align__(16) uint8_t dsm[];
    int mat = blockIdx.y;
    const __half* A = mat ? gv : gk;
    const __half* B = mat ? Wvh : Wkh;
    float* C = mat ? KVv : KVk;

    int tid = threadIdx.x, wid = tid >> 5, lane = tid & 31;
    int n0g = blockIdx.x * 128;
    int m0w = (wid & 1) * 32, n0w = (wid >> 1) * 32;
    uint32_t sbase = smem_u32(dsm);
    uint32_t a_off = (lane % 16) * STR + (lane / 16) * 16;
    uint32_t b_off = ((lane & 7) + ((lane >> 4) << 3)) * STR + ((lane >> 3) & 1) * 16;
    float acc[2][4][4] = {};

    int nchunk = Kd / 32;
    auto load_chunk = [&](int c, int sel) {
        uint32_t bb = sbase + sel * PBUFB;
        int k0 = c * 32;
        {
            int row = tid >> 2, seg = tid & 3;
            CP_ASYNC16(bb + POA + row * STR + seg * 16,
                       A + (size_t)row * Kd + k0 + seg * 8);
        }
        #pragma unroll
        for (int q = 0; q < 2; q++) {
            int p = tid + q * 256;
            int row = p >> 2, seg = p & 3;
            CP_ASYNC16(bb + POB + row * STR + seg * 16,
                       B + (size_t)(n0g + row) * Kd + k0 + seg * 8);
        }
    };

    load_chunk(0, 0); CP_COMMIT();
    load_chunk(1, 1); CP_COMMIT();

    for (int c = 0; c < nchunk; c++) {
        CP_WAIT(1);
        __syncthreads();
        if (c + 2 < nchunk) load_chunk(c + 2, (c + 2) % 3);
        CP_COMMIT();

        uint32_t bb = sbase + (c % 3) * PBUFB;
        #pragma unroll
        for (int ks = 0; ks < 2; ks++) {
            uint32_t a[2][4], b[2][4];
            #pragma unroll
            for (int mf = 0; mf < 2; mf++)
                ldsm_x4(a[mf], bb + POA + (m0w + mf * 16) * STR + ks * 32 + a_off);
            #pragma unroll
            for (int ng = 0; ng < 2; ng++)
                ldsm_x4(b[ng], bb + POB + (n0w + ng * 16) * STR + ks * 32 + b_off);
            #pragma unroll
            for (int mf = 0; mf < 2; mf++)
                #pragma unroll
                for (int nf = 0; nf < 4; nf++)
                    mma_f16(acc[mf][nf], a[mf], &b[nf >> 1][(nf & 1) * 2]);
        }
    }

    #pragma unroll
    for (int mf = 0; mf < 2; mf++)
        #pragma unroll
        for (int nf = 0; nf < 4; nf++) {
            int col = n0g + n0w + nf * 8 + (lane & 3) * 2;
            int r0 = m0w + mf * 16 + (lane >> 2);
            *(float2*)(C + (size_t)r0 * D_MAX + col) =
                make_float2(acc[mf][nf][0], acc[mf][nf][1]);
            *(float2*)(C + (size_t)(r0 + 8) * D_MAX + col) =
                make_float2(acc[mf][nf][2], acc[mf][nf][3]);
        }
}

// ---------------------------------------------------------------------------
// fp16 single-term HMMA GEMM with row offset
// ---------------------------------------------------------------------------
#define OA 0
#define OB 10240
#define BUFB 20480
#define GEMM_DSMEM (3 * BUFB)

__global__ void __launch_bounds__(512) gemm_hmma_kernel(
        const __half* __restrict__ Ah, const __half* __restrict__ Bh,
        const float* __restrict__ bias, float* __restrict__ C, int Kd, int Nc, int mbase) {
    extern __shared__ __align__(16) uint8_t dsm[];
    int tid = threadIdx.x, wid = tid >> 5, lane = tid & 31;
    int m0g = mbase + blockIdx.y * 128, n0g = blockIdx.x * 128;
    int m0w = (wid & 3) * 32, n0w = (wid >> 2) * 32;
    uint32_t sbase = smem_u32(dsm);
    uint32_t a_off = (lane % 16) * STR + (lane / 16) * 16;
    uint32_t b_off = ((lane & 7) + ((lane >> 4) << 3)) * STR + ((lane >> 3) & 1) * 16;
    float acc[2][4][4] = {};

    int nchunk = Kd / 32;
    int lrow = tid >> 2, lseg = tid & 3;
    uint32_t lso = lrow * STR + lseg * 16;
    auto load_chunk = [&](int c, int sel) {
        uint32_t bb = sbase + sel * BUFB;
        int k0 = c * 32;
        size_t ga = (size_t)(m0g + lrow) * Kd + k0 + lseg * 8;
        size_t gb = (size_t)(n0g + lrow) * Kd + k0 + lseg * 8;
        CP_ASYNC16(bb + OA + lso, Ah + ga);
        CP_ASYNC16(bb + OB + lso, Bh + gb);
    };

    load_chunk(0, 0); CP_COMMIT();
    load_chunk(1, 1); CP_COMMIT();

    for (int c = 0; c < nchunk; c++) {
        CP_WAIT(1);
        __syncthreads();
        if (c + 2 < nchunk) load_chunk(c + 2, (c + 2) % 3);
        CP_COMMIT();

        uint32_t bb = sbase + (c % 3) * BUFB;
        #pragma unroll
        for (int ks = 0; ks < 2; ks++) {
            uint32_t a[2][4], b[2][4];
            #pragma unroll
            for (int mf = 0; mf < 2; mf++)
                ldsm_x4(a[mf], bb + OA + (m0w + mf * 16) * STR + ks * 32 + a_off);
            #pragma unroll
            for (int ng = 0; ng < 2; ng++)
                ldsm_x4(b[ng], bb + OB + (n0w + ng * 16) * STR + ks * 32 + b_off);
            #pragma unroll
            for (int mf = 0; mf < 2; mf++)
                #pragma unroll
                for (int nf = 0; nf < 4; nf++)
                    mma_f16(acc[mf][nf], a[mf], &b[nf >> 1][(nf & 1) * 2]);
        }
    }

    #pragma unroll
    for (int mf = 0; mf < 2; mf++)
        #pragma unroll
        for (int nf = 0; nf < 4; nf++) {
            int col = n0g + n0w + nf * 8 + (lane & 3) * 2;
            float b0 = bias ? bias[col]     : 0.f;
            float b1 = bias ? bias[col + 1] : 0.f;
            int r0 = m0g + m0w + mf * 16 + (lane >> 2);
            float2 v0 = {acc[mf][nf][0] + b0, acc[mf][nf][1] + b1};
            float2 v1 = {acc[mf][nf][2] + b0, acc[mf][nf][3] + b1};
            *(float2*)(C + (size_t)r0 * Nc + col)       = v0;
            *(float2*)(C + (size_t)(r0 + 8) * Nc + col) = v1;
        }
}

// ---------------------------------------------------------------------------
// per-row attention (row0 offset); ctx emitted as fp16 for gemm2
// ---------------------------------------------------------------------------
__global__ void __launch_bounds__(256) attn_kernel(
        const float* __restrict__ qfull,
        const float* __restrict__ Kp, const float* __restrict__ Kn,
        const float* __restrict__ Vp, const float* __restrict__ Vn,
        const int* __restrict__ pos, const int* __restrict__ neg,
        const int* __restrict__ sgn,
        __half* __restrict__ ctxh,
        float* __restrict__ avg_out, float* __restrict__ sel_out,
        int D, float scale, int row0) {
    int rn = row0 + blockIdx.x;
    int tid = threadIdx.x;
    int warp = tid >> 5, lane = tid & 31;
    __shared__ float qs[D_MAX];
    __shared__ float sc[NHEADS * TKK];

    int sg = sgn[rn];
    const float* Km = sg ? Kp : Kn;
    const float* Vm = sg ? Vp : Vn;
    const int* idx  = sg ? pos : neg;

    for (int j = tid * 4; j < D; j += 1024)
        *(float4*)(qs + j) = *(const float4*)(qfull + (size_t)rn * D + j);
    __syncthreads();

    for (int t = 0; t < 64; t++) {
        int p = warp * 64 + t;
        int h = p >> 5, k = p & 31;
        const float* kr = Km + (size_t)k * D_MAX + h * 64;
        const float* qr = qs + h * 64;
        float v = qr[lane] * kr[lane] + qr[lane + 32] * kr[lane + 32];
        #pragma unroll
        for (int off = 16; off; off >>= 1) v += __shfl_xor_sync(0xffffffffu, v, off);
        if (lane == 0) sc[p] = v * scale;
    }
    __syncthreads();

    #pragma unroll
    for (int hh = warp * 2; hh < warp * 2 + 2; hh++) {
        float v = sc[hh * 32 + lane];
        float mx = v;
        #pragma unroll
        for (int off = 16; off; off >>= 1) mx = fmaxf(mx, __shfl_xor_sync(0xffffffffu, mx, off));
        float e = expf(v - mx);
        float s = e;
        #pragma unroll
        for (int off = 16; off; off >>= 1) s += __shfl_xor_sync(0xffffffffu, s, off);
        sc[hh * 32 + lane] = e / s;
    }
    __syncthreads();

    if (tid < 32) {
        if (avg_out) {
            float a = 0.f;
            #pragma unroll
            for (int h = 0; h < NHEADS; h++) a += sc[h * 32 + tid];
            avg_out[(size_t)rn * TKK + tid] = a * (1.f / NHEADS);
        }
        if (sel_out) sel_out[(size_t)rn * TKK + tid] = (float)idx[tid];
    }

    for (int o = tid; o < D; o += 256) {
        int h = o >> 6;
        const float* arow = sc + h * 32;
        float a = 0.f;
        #pragma unroll
        for (int k = 0; k < TKK; k++) a += arow[k] * Vm[(size_t)k * D_MAX + o];
        ctxh[(size_t)rn * D + o] = __float2half_rn(a);
    }
}

// ---------------------------------------------------------------------------
// LayerNorm in-place per row (row0 offset)
// ---------------------------------------------------------------------------
__global__ void __launch_bounds__(256) ln_kernel(
        float* __restrict__ out, const float* __restrict__ gamma,
        const float* __restrict__ beta, int D, float eps, int row0) {
    int rn = row0 + blockIdx.x;
    float* row = out + (size_t)rn * D;
    int tid = threadIdx.x;
    int warp = tid >> 5, lane = tid & 31;
    __shared__ float ssum[8], ssq[8];

    float s = 0.f, ss = 0.f;
    for (int j = tid * 4; j < D; j += 1024) {
        float4 v = *(const float4*)(row + j);
        s  += v.x + v.y + v.z + v.w;
        ss += v.x * v.x + v.y * v.y + v.z * v.z + v.w * v.w;
    }
    #pragma unroll
    for (int off = 16; off; off >>= 1) {
        s  += __shfl_xor_sync(0xffffffffu, s, off);
        ss += __shfl_xor_sync(0xffffffffu, ss, off);
    }
    if (lane == 0) { ssum[warp] = s; ssq[warp] = ss; }
    __syncthreads();
    if (tid == 0) {
        float ts = 0.f, tq = 0.f;
        #pragma unroll
        for (int w = 0; w < 8; w++) { ts += ssum[w]; tq += ssq[w]; }
        ssum[0] = ts; ssq[0] = tq;
    }
    __syncthreads();
    float mu = ssum[0] / D;
    float var = ssq[0] / D - mu * mu;
    float rstd = rsqrtf(var + eps);
    for (int j = tid * 4; j < D; j += 1024) {
        float4 v = *(const float4*)(row + j);
        float4 g = *(const float4*)(gamma + j);
        float4 bb = *(const float4*)(beta + j);
        v.x = (v.x - mu) * rstd * g.x + bb.x;
        v.y = (v.y - mu) * rstd * g.y + bb.y;
        v.z = (v.z - mu) * rstd * g.z + bb.z;
        v.w = (v.w - mu) * rstd * g.w + bb.w;
        *(float4*)(row + j) = v;
    }
}

// ---------------------------------------------------------------------------
// launch — forked graph + pipelined post-join
// ---------------------------------------------------------------------------
extern "C" void kernel_launch(void* const* d_in, const int* in_sizes, int n_in,
                              void* d_out, int out_size) {
    const float* x     = (const float*)d_in[0];
    const float* mk    = (const float*)d_in[1];
    const float* mv    = (const float*)d_in[2];
    const float* Wq    = (const float*)d_in[3];
    const float* Wk    = (const float*)d_in[4];
    const float* Wv    = (const float*)d_in[5];
    const float* Wo    = (const float*)d_in[6];
    const float* bo    = (const float*)d_in[7];
    const float* gamma = (const float*)d_in[8];
    const float* beta  = (const float*)d_in[9];

    int D    = in_sizes[7];
    int rows = in_sizes[0] / D;           // B*N
    int M    = in_sizes[1] / D;
    int hd   = D / NHEADS;
    int half = rows / 2;

    float* out = (float*)d_out;
    float* avg_out = nullptr;
    float* sel_out = nullptr;
    if ((long long)out_size >= (long long)rows * (D + 2 * TKK)) {
        avg_out = out + (size_t)rows * D;
        sel_out = avg_out + (size_t)rows * TKK;
    }

    float *p_r, *p_wbar, *p_part, *p_KVk, *p_KVv, *p_qf;
    int *p_pos, *p_neg, *p_sgn;
    unsigned long long* p_cand;
    __half *p_xh, *p_ch, *p_Wqh, *p_Woh, *p_Wkh, *p_Wvh, *p_gk, *p_gv;
    cudaGetSymbolAddress((void**)&p_r,    g_r);
    cudaGetSymbolAddress((void**)&p_wbar, g_wbar);
    cudaGetSymbolAddress((void**)&p_part, g_colpart);
    cudaGetSymbolAddress((void**)&p_pos,  g_posidx);
    cudaGetSymbolAddress((void**)&p_neg,  g_negidx);
    cudaGetSymbolAddress((void**)&p_sgn,  g_sign);
    cudaGetSymbolAddress((void**)&p_cand, g_cand);
    cudaGetSymbolAddress((void**)&p_KVk,  g_KVk);
    cudaGetSymbolAddress((void**)&p_KVv,  g_KVv);
    cudaGetSymbolAddress((void**)&p_qf,   g_qfull);
    cudaGetSymbolAddress((void**)&p_xh,   g_xh);
    cudaGetSymbolAddress((void**)&p_ch,   g_ch);
    cudaGetSymbolAddress((void**)&p_Wqh,  g_Wqh);
    cudaGetSymbolAddress((void**)&p_Woh,  g_Woh);
    cudaGetSymbolAddress((void**)&p_Wkh,  g_Wkh);
    cudaGetSymbolAddress((void**)&p_Wvh,  g_Wvh);
    cudaGetSymbolAddress((void**)&p_gk,   g_gk);
    cudaGetSymbolAddress((void**)&p_gv,   g_gv);

    float* p_Kp = p_KVk;
    float* p_Kn = p_KVk + 32 * D_MAX;
    float* p_Vp = p_KVv;
    float* p_Vn = p_KVv + 32 * D_MAX;

    cudaFuncSetAttribute(gemm_hmma_kernel, cudaFuncAttributeMaxDynamicSharedMemorySize,
                         GEMM_DSMEM);
    cudaFuncSetAttribute(projgemm_kernel, cudaFuncAttributeMaxDynamicSharedMemorySize,
                         PROJ_DSMEM);

    static cudaStream_t sA = nullptr, sB = nullptr;
    static cudaEvent_t e0 = nullptr, eA = nullptr, eB = nullptr, eW = nullptr,
                       eC1 = nullptr, eD1 = nullptr;
    if (!sA) {
        cudaStreamCreateWithFlags(&sA, cudaStreamNonBlocking);
        cudaStreamCreateWithFlags(&sB, cudaStreamNonBlocking);
        cudaEventCreateWithFlags(&e0, cudaEventDisableTiming);
        cudaEventCreateWithFlags(&eA, cudaEventDisableTiming);
        cudaEventCreateWithFlags(&eB, cudaEventDisableTiming);
        cudaEventCreateWithFlags(&eW, cudaEventDisableTiming);
        cudaEventCreateWithFlags(&eC1, cudaEventDisableTiming);
        cudaEventCreateWithFlags(&eD1, cudaEventDisableTiming);
    }

    float sqrtD = sqrtf((float)D);
    float scale = 1.f / sqrtf((float)hd);
    int nx4 = rows * D / 4, nw4 = D * D / 4;
    int segs = (M + 1023) / 1024;

    // ---- fork ----
    cudaEventRecord(e0, 0);
    cudaStreamWaitEvent(sA, e0, 0);
    cudaStreamWaitEvent(sB, e0, 0);

    // side B front: Wk/Wv/Wo fp16 converts (one batched launch)
    cvtW3_kernel<<<dim3((nw4 + 255) / 256, 3), 256, 0, sB>>>(
        Wk, Wv, Wo, p_Wkh, p_Wvh, p_Woh, nw4);
    cudaEventRecord(eW, sB);

    // side A: rowstat -> topk -> gather -> projgemm
    rowstat_kernel<<<(M + 15) / 16, 256, 0, sA>>>(mk, p_r, M, D, sqrtD);
    topk_stage1<<<dim3(segs, 2), 256, 0, sA>>>(p_r, M, p_cand);
    topk_stage2<<<2, 32, 0, sA>>>(p_cand, segs, p_pos, p_neg);
    cudaStreamWaitEvent(sA, eW, 0);
    gather_kernel<<<dim3(64, 2), 256, 0, sA>>>(mk, mv, p_pos, p_neg, p_gk, p_gv, D);
    projgemm_kernel<<<dim3(D / 128, 2), 256, PROJ_DSMEM, sA>>>(
        p_gk, p_gv, p_Wkh, p_Wvh, p_KVk, p_KVv, D);
    cudaEventRecord(eA, sA);

    // side B rest: colsum -> qmsign
    colsum1_kernel<<<dim3((D + 255) / 256, 32), 256, 0, sB>>>(Wq, p_part, D);
    colsum2_kernel<<<(D + 255) / 256, 256, 0, sB>>>(p_part, p_wbar, D);
    qmsign_kernel<<<(rows + 7) / 8, 256, 0, sB>>>(x, p_wbar, p_sgn, rows, D);
    cudaEventRecord(eB, sB);

    // main: x/Wq converts -> gemm1 (all rows)
    cvt_kernel<<<(nx4 + 255) / 256, 256>>>(x,  p_xh,  nx4);
    cvt_kernel<<<(nw4 + 255) / 256, 256>>>(Wq, p_Wqh, nw4);
    gemm_hmma_kernel<<<dim3(D / 128, rows / 128), 512, GEMM_DSMEM>>>(
        p_xh, p_Wqh, nullptr, p_qf, D, D, 0);

    // ---- join ----
    cudaStreamWaitEvent(0, eA, 0);
    cudaStreamWaitEvent(0, eB, 0);

    // pipelined tail: half1 attn -> (sA: gemm2a+ln_a) while main does half2
    attn_kernel<<<half, 256>>>(p_qf, p_Kp, p_Kn, p_Vp, p_Vn, p_pos, p_neg, p_sgn,
                               p_ch, avg_out, sel_out, D, scale, 0);
    cudaEventRecord(eC1, 0);

    cudaStreamWaitEvent(sA, eC1, 0);
    gemm_hmma_kernel<<<dim3(D / 128, half / 128), 512, GEMM_DSMEM, sA>>>(
        p_ch, p_Woh, bo, out, D, D, 0);
    ln_kernel<<<half, 256, 0, sA>>>(out, gamma, beta, D, 1e-5f, 0);
    cudaEventRecord(eD1, sA);

    attn_kernel<<<half, 256>>>(p_qf, p_Kp, p_Kn, p_Vp, p_Vn, p_pos, p_neg, p_sgn,
                               p_ch, avg_out, sel_out, D, scale, half);
    gemm_hmma_kernel<<<dim3(D / 128, half / 128), 512, GEMM_DSMEM>>>(
        p_ch, p_Woh, bo, out, D, D, half);
    ln_kernel<<<half, 256>>>(out, gamma, beta, D, 1e-5f, half);

    cudaStreamWaitEvent(0, eD1, 0);
}

// round 17
// speedup vs baseline: 1.1220x; 1.1220x over previous
#include <cuda_runtime.h>
#include <cuda_bf16.h>
#include <cuda_fp16.h>
#include <math.h>
#include <stdint.h>

// ============================================================================
// CrossAttentionReader — GB300 sm_103a, round 17
//  - base: round-15 tail (165.3us; round-16 split reverted)
//  - kept: rowstat 2-row/warp, batched Wk/Wv/Wo convert
//  - topk_stage2 tree-parallelized (13.9us single-warp chain -> ~2.5us)
// ============================================================================

#define D_MAX     1024
#define M_MAX     32768
#define ROWS_MAX  2048
#define TKK       32
#define NHEADS    16

// ---- scratch (device globals; no allocation allowed) ----
__device__ float g_r[M_MAX];
__device__ float g_wbar[D_MAX];
__device__ float g_colpart[32 * D_MAX];
__device__ int   g_posidx[TKK];
__device__ int   g_negidx[TKK];
__device__ int   g_sign[ROWS_MAX];
__device__ unsigned long long g_cand[2 * 1024];
__device__ __half g_gk[64 * D_MAX];
__device__ __half g_gv[64 * D_MAX];
__device__ float g_KVk[64 * D_MAX];          // rows 0-31: Kp, 32-63: Kn
__device__ float g_KVv[64 * D_MAX];          // rows 0-31: Vp, 32-63: Vn
__device__ float g_qfull[(size_t)ROWS_MAX * D_MAX];
__device__ __half g_xh[(size_t)ROWS_MAX * D_MAX];
__device__ __half g_ch[(size_t)ROWS_MAX * D_MAX];
__device__ __half g_Wqh[(size_t)D_MAX * D_MAX];
__device__ __half g_Woh[(size_t)D_MAX * D_MAX];
__device__ __half g_Wkh[(size_t)D_MAX * D_MAX];
__device__ __half g_Wvh[(size_t)D_MAX * D_MAX];

// ============================ helpers ===================================
__device__ __forceinline__ uint32_t smem_u32(const void* p) {
    uint32_t a;
    asm("{ .reg .u64 t; cvta.to.shared.u64 t, %1; cvt.u32.u64 %0, t; }" : "=r"(a) : "l"(p));
    return a;
}
__device__ __forceinline__ void ldsm_x4(uint32_t* r, uint32_t addr) {
    asm volatile("ldmatrix.sync.aligned.m8n8.x4.shared.b16 {%0,%1,%2,%3}, [%4];"
                 : "=r"(r[0]), "=r"(r[1]), "=r"(r[2]), "=r"(r[3]) : "r"(addr));
}
__device__ __forceinline__ void mma_f16(float* d, const uint32_t* a, const uint32_t* b) {
    asm volatile("mma.sync.aligned.m16n8k16.row.col.f32.f16.f16.f32 "
                 "{%0,%1,%2,%3}, {%4,%5,%6,%7}, {%8,%9}, {%0,%1,%2,%3};"
                 : "+f"(d[0]), "+f"(d[1]), "+f"(d[2]), "+f"(d[3])
                 : "r"(a[0]), "r"(a[1]), "r"(a[2]), "r"(a[3]), "r"(b[0]), "r"(b[1]));
}
#define CP_ASYNC16(sa, gp) \
    asm volatile("cp.async.cg.shared.global [%0], [%1], 16;" :: "r"(sa), "l"(gp))
#define CP_COMMIT() asm volatile("cp.async.commit_group;" ::: "memory")
#define CP_WAIT(n)  asm volatile("cp.async.wait_group %0;" :: "n"(n) : "memory")

// warp bitonic: sort 32 u64 keys (one per lane) descending
__device__ __forceinline__ unsigned long long bsort32_desc(unsigned long long key, int lane) {
    #pragma unroll
    for (int k = 2; k <= 32; k <<= 1) {
        #pragma unroll
        for (int j = 16; j > 0; j >>= 1) {
            if (j >= k) continue;
            unsigned long long other = __shfl_xor_sync(0xffffffffu, key, j);
            bool keepMax = (((lane & j) == 0) == ((lane & k) == 0));
            bool gt = key > other;
            key = (keepMax == gt) ? key : other;
        }
    }
    return key;
}

__device__ __forceinline__ unsigned long long bmerge_top32(unsigned long long a,
                                                           unsigned long long b, int lane) {
    unsigned long long brev = __shfl_sync(0xffffffffu, b, 31 - lane);
    unsigned long long k = (a > brev) ? a : brev;
    #pragma unroll
    for (int j = 16; j > 0; j >>= 1) {
        unsigned long long other = __shfl_xor_sync(0xffffffffu, k, j);
        bool keepMax = ((lane & j) == 0);
        bool gt = k > other;
        k = (keepMax == gt) ? k : other;
    }
    return k;
}

// ---------------------------------------------------------------------------
// convert fp32 -> fp16 (single)
// ---------------------------------------------------------------------------
__global__ void cvt_kernel(const float* __restrict__ src, __half* __restrict__ dst, int n4) {
    int i = blockIdx.x * 256 + threadIdx.x;
    if (i >= n4) return;
    float4 v = ((const float4*)src)[i];
    __half2 a = __floats2half2_rn(v.x, v.y);
    __half2 b = __floats2half2_rn(v.z, v.w);
    ((__half2*)dst)[2 * i]     = a;
    ((__half2*)dst)[2 * i + 1] = b;
}

// batched convert of 3 weight matrices (grid.y selects)
__global__ void cvtW3_kernel(const float* __restrict__ Wk, const float* __restrict__ Wv,
                             const float* __restrict__ Wo,
                             __half* __restrict__ dk, __half* __restrict__ dv,
                             __half* __restrict__ dwo, int n4) {
    int i = blockIdx.x * 256 + threadIdx.x;
    if (i >= n4) return;
    const float* src = (blockIdx.y == 0) ? Wk : (blockIdx.y == 1) ? Wv : Wo;
    __half* dst      = (blockIdx.y == 0) ? dk : (blockIdx.y == 1) ? dv : dwo;
    float4 v = ((const float4*)src)[i];
    __half2 a = __floats2half2_rn(v.x, v.y);
    __half2 b = __floats2half2_rn(v.z, v.w);
    ((__half2*)dst)[2 * i]     = a;
    ((__half2*)dst)[2 * i + 1] = b;
}

// ---------------------------------------------------------------------------
// gather selected memory rows -> fp16 [64][1024]
// ---------------------------------------------------------------------------
__global__ void gather_kernel(const float* __restrict__ mk, const float* __restrict__ mv,
                              const int* __restrict__ pos, const int* __restrict__ neg,
                              __half* __restrict__ gk, __half* __restrict__ gv, int D) {
    int slot = blockIdx.x, mat = blockIdx.y;
    const float* src = mat ? mv : mk;
    __half* dst = mat ? gv : gk;
    int row = (slot < 32) ? pos[slot] : neg[slot - 32];
    const float* s = src + (size_t)row * D;
    __half* d = dst + (size_t)slot * D_MAX;
    int j = threadIdx.x * 4;
    float4 v = *(const float4*)(s + j);
    __half2 a = __floats2half2_rn(v.x, v.y);
    __half2 b = __floats2half2_rn(v.z, v.w);
    ((__half2*)d)[threadIdx.x * 2]     = a;
    ((__half2*)d)[threadIdx.x * 2 + 1] = b;
}

// ---------------------------------------------------------------------------
// column sum of Wq — two-stage deterministic reduction (32-way row split)
// ---------------------------------------------------------------------------
__global__ void colsum1_kernel(const float* __restrict__ W, float* __restrict__ part, int D) {
    int d = blockIdx.x * 256 + threadIdx.x;
    if (d >= D) return;
    int r0 = blockIdx.y * 32;
    float s = 0.f;
    for (int r = r0; r < r0 + 32; r++) s += W[(size_t)r * D + d];
    part[blockIdx.y * D + d] = s;
}
__global__ void colsum2_kernel(const float* __restrict__ part, float* __restrict__ wbar, int D) {
    int d = blockIdx.x * 256 + threadIdx.x;
    if (d >= D) return;
    float s = 0.f;
    #pragma unroll
    for (int i = 0; i < 32; i++) s += part[i * D + d];
    wbar[d] = s;
}

// ---------------------------------------------------------------------------
// per-row r[m] = sum / (sqrtD * norm) — 2 rows per warp for 2x MLP
// ---------------------------------------------------------------------------
__global__ void rowstat_kernel(const float* __restrict__ mk, float* __restrict__ r,
                               int M, int D, float sqrtD) {
    int warp = threadIdx.x >> 5, lane = threadIdx.x & 31;
    int m0 = blockIdx.x * 16 + warp * 2;
    if (m0 >= M) return;
    const float* row0 = mk + (size_t)m0 * D;
    const float* row1 = mk + (size_t)(m0 + 1) * D;
    float s0 = 0.f, q0 = 0.f, s1 = 0.f, q1 = 0.f;
    for (int j = lane * 4; j < D; j += 128) {
        float4 a = *(const float4*)(row0 + j);
        float4 b = *(const float4*)(row1 + j);
        s0 += a.x + a.y + a.z + a.w;
        q0 += a.x * a.x + a.y * a.y + a.z * a.z + a.w * a.w;
        s1 += b.x + b.y + b.z + b.w;
        q1 += b.x * b.x + b.y * b.y + b.z * b.z + b.w * b.w;
    }
    #pragma unroll
    for (int off = 16; off; off >>= 1) {
        s0 += __shfl_xor_sync(0xffffffffu, s0, off);
        q0 += __shfl_xor_sync(0xffffffffu, q0, off);
        s1 += __shfl_xor_sync(0xffffffffu, s1, off);
        q1 += __shfl_xor_sync(0xffffffffu, q1, off);
    }
    if (lane == 0) {
        r[m0] = s0 / (sqrtD * sqrtf(q0));
        if (m0 + 1 < M) r[m0 + 1] = s1 / (sqrtD * sqrtf(q1));
    }
}

// ---------------------------------------------------------------------------
// sign(qm) per row
// ---------------------------------------------------------------------------
__global__ void qmsign_kernel(const float* __restrict__ x, const float* __restrict__ wbar,
                              int* __restrict__ sgn, int rows, int D) {
    int warp = threadIdx.x >> 5, lane = threadIdx.x & 31;
    int rn = blockIdx.x * 8 + warp;
    if (rn >= rows) return;
    const float* row = x + (size_t)rn * D;
    float s = 0.f;
    for (int j = lane * 4; j < D; j += 128) {
        float4 v = *(const float4*)(row + j);
        float4 w = *(const float4*)(wbar + j);
        s += v.x * w.x + v.y * w.y + v.z * w.z + v.w * w.w;
    }
    #pragma unroll
    for (int off = 16; off; off >>= 1) s += __shfl_xor_sync(0xffffffffu, s, off);
    if (lane == 0) sgn[rn] = (s >= 0.f) ? 1 : 0;
}

// ---------------------------------------------------------------------------
// topk: warp-register bitonic top-32
// ---------------------------------------------------------------------------
__global__ void topk_stage1(const float* __restrict__ r, int M,
                            unsigned long long* __restrict__ cand) {
    int mode = blockIdx.y, seg = blockIdx.x;
    int tid = threadIdx.x, warp = tid >> 5, lane = tid & 31;
    __shared__ unsigned long long wres[8][32];

    unsigned long long best = 0ull;
    #pragma unroll
    for (int c = 0; c < 4; c++) {
        int gi = seg * 1024 + warp * 128 + c * 32 + lane;
        unsigned long long key = 0ull;
        if (gi < M) {
            uint32_t b = __float_as_uint(r[gi]);
            uint32_t u = (b & 0x80000000u) ? ~b : (b | 0x80000000u);
            if (mode) u = ~u;
            key = ((unsigned long long)u << 32) | (uint32_t)(~gi);
        }
        key = bsort32_desc(key, lane);
        best = (c == 0) ? key : bmerge_top32(best, key, lane);
    }
    wres[warp][lane] = best;
    __syncthreads();
    if (warp == 0) {
        unsigned long long m01 = bmerge_top32(wres[0][lane], wres[1][lane], lane);
        unsigned long long m23 = bmerge_top32(wres[2][lane], wres[3][lane], lane);
        unsigned long long m45 = bmerge_top32(wres[4][lane], wres[5][lane], lane);
        unsigned long long m67 = bmerge_top32(wres[6][lane], wres[7][lane], lane);
        unsigned long long mA  = bmerge_top32(m01, m23, lane);
        unsigned long long mB  = bmerge_top32(m45, m67, lane);
        cand[mode * 1024 + seg * 32 + lane] = bmerge_top32(mA, mB, lane);
    }
}

// stage 2: 8 warps tree-merge the nlists segment top-32 lists (per mode)
__global__ void topk_stage2(const unsigned long long* __restrict__ cand, int nlists,
                            int* __restrict__ pos, int* __restrict__ neg) {
    int mode = blockIdx.x;
    int tid = threadIdx.x, warp = tid >> 5, lane = tid & 31;
    __shared__ unsigned long long wres[8][32];

    // each warp merges lists [warp], [warp+8], [warp+16], ...
    unsigned long long acc = (warp < nlists) ? cand[mode * 1024 + warp * 32 + lane] : 0ull;
    for (int l = warp + 8; l < nlists; l += 8)
        acc = bmerge_top32(acc, cand[mode * 1024 + l * 32 + lane], lane);
    wres[warp][lane] = acc;
    __syncthreads();
    if (warp == 0) {
        unsigned long long m01 = bmerge_top32(wres[0][lane], wres[1][lane], lane);
        unsigned long long m23 = bmerge_top32(wres[2][lane], wres[3][lane], lane);
        unsigned long long m45 = bmerge_top32(wres[4][lane], wres[5][lane], lane);
        unsigned long long m67 = bmerge_top32(wres[6][lane], wres[7][lane], lane);
        unsigned long long mA  = bmerge_top32(m01, m23, lane);
        unsigned long long mB  = bmerge_top32(m45, m67, lane);
        unsigned long long top = bmerge_top32(mA, mB, lane);
        int idx = (int)(~(uint32_t)(top & 0xffffffffu));
        (mode ? neg : pos)[lane] = idx;
    }
}

// ---------------------------------------------------------------------------
// proj GEMM (fp16 HMMA): C[64,1024] = gath[64,1024] @ W[1024,1024]^T
// ---------------------------------------------------------------------------
#define STR 80
#define POA 0
#define POB 5120
#define PBUFB 15360
#define PROJ_DSMEM (3 * PBUFB)

__global__ void __launch_bounds__(256) projgemm_kernel(
        const __half* __restrict__ gk, const __half* __restrict__ gv,
        const __half* __restrict__ Wkh, const __half* __restrict__ Wvh,
        float* __restrict__ KVk, float* __restrict__ KVv, int Kd) {
    extern __shared__ __align__(16) uint8_t dsm[];
    int mat = blockIdx.y;
    const __half* A = mat ? gv : gk;
    const __half* B = mat ? Wvh : Wkh;
    float* C = mat ? KVv : KVk;

    int tid = threadIdx.x, wid = tid >> 5, lane = tid & 31;
    int n0g = blockIdx.x * 128;
    int m0w = (wid & 1) * 32, n0w = (wid >> 1) * 32;
    uint32_t sbase = smem_u32(dsm);
    uint32_t a_off = (lane % 16) * STR + (lane / 16) * 16;
    uint32_t b_off = ((lane & 7) + ((lane >> 4) << 3)) * STR + ((lane >> 3) & 1) * 16;
    float acc[2][4][4] = {};

    int nchunk = Kd / 32;
    auto load_chunk = [&](int c, int sel) {
        uint32_t bb = sbase + sel * PBUFB;
        int k0 = c * 32;
        {
            int row = tid >> 2, seg = tid & 3;
            CP_ASYNC16(bb + POA + row * STR + seg * 16,
                       A + (size_t)row * Kd + k0 + seg * 8);
        }
        #pragma unroll
        for (int q = 0; q < 2; q++) {
            int p = tid + q * 256;
            int row = p >> 2, seg = p & 3;
            CP_ASYNC16(bb + POB + row * STR + seg * 16,
                       B + (size_t)(n0g + row) * Kd + k0 + seg * 8);
        }
    };

    load_chunk(0, 0); CP_COMMIT();
    load_chunk(1, 1); CP_COMMIT();

    for (int c = 0; c < nchunk; c++) {
        CP_WAIT(1);
        __syncthreads();
        if (c + 2 < nchunk) load_chunk(c + 2, (c + 2) % 3);
        CP_COMMIT();

        uint32_t bb = sbase + (c % 3) * PBUFB;
        #pragma unroll
        for (int ks = 0; ks < 2; ks++) {
            uint32_t a[2][4], b[2][4];
            #pragma unroll
            for (int mf = 0; mf < 2; mf++)
                ldsm_x4(a[mf], bb + POA + (m0w + mf * 16) * STR + ks * 32 + a_off);
            #pragma unroll
            for (int ng = 0; ng < 2; ng++)
                ldsm_x4(b[ng], bb + POB + (n0w + ng * 16) * STR + ks * 32 + b_off);
            #pragma unroll
            for (int mf = 0; mf < 2; mf++)
                #pragma unroll
                for (int nf = 0; nf < 4; nf++)
                    mma_f16(acc[mf][nf], a[mf], &b[nf >> 1][(nf & 1) * 2]);
        }
    }

    #pragma unroll
    for (int mf = 0; mf < 2; mf++)
        #pragma unroll
        for (int nf = 0; nf < 4; nf++) {
            int col = n0g + n0w + nf * 8 + (lane & 3) * 2;
            int r0 = m0w + mf * 16 + (lane >> 2);
            *(float2*)(C + (size_t)r0 * D_MAX + col) =
                make_float2(acc[mf][nf][0], acc[mf][nf][1]);
            *(float2*)(C + (size_t)(r0 + 8) * D_MAX + col) =
                make_float2(acc[mf][nf][2], acc[mf][nf][3]);
        }
}

// ---------------------------------------------------------------------------
// fp16 single-term HMMA GEMM
// ---------------------------------------------------------------------------
#define OA 0
#define OB 10240
#define BUFB 20480
#define GEMM_DSMEM (3 * BUFB)

__global__ void __launch_bounds__(512) gemm_hmma_kernel(
        const __half* __restrict__ Ah, const __half* __restrict__ Bh,
        const float* __restrict__ bias, float* __restrict__ C, int Kd, int Nc) {
    extern __shared__ __align__(16) uint8_t dsm[];
    int tid = threadIdx.x, wid = tid >> 5, lane = tid & 31;
    int m0g = blockIdx.y * 128, n0g = blockIdx.x * 128;
    int m0w = (wid & 3) * 32, n0w = (wid >> 2) * 32;
    uint32_t sbase = smem_u32(dsm);
    uint32_t a_off = (lane % 16) * STR + (lane / 16) * 16;
    uint32_t b_off = ((lane & 7) + ((lane >> 4) << 3)) * STR + ((lane >> 3) & 1) * 16;
    float acc[2][4][4] = {};

    int nchunk = Kd / 32;
    int lrow = tid >> 2, lseg = tid & 3;
    uint32_t lso = lrow * STR + lseg * 16;
    auto load_chunk = [&](int c, int sel) {
        uint32_t bb = sbase + sel * BUFB;
        int k0 = c * 32;
        size_t ga = (size_t)(m0g + lrow) * Kd + k0 + lseg * 8;
        size_t gb = (size_t)(n0g + lrow) * Kd + k0 + lseg * 8;
        CP_ASYNC16(bb + OA + lso, Ah + ga);
        CP_ASYNC16(bb + OB + lso, Bh + gb);
    };

    load_chunk(0, 0); CP_COMMIT();
    load_chunk(1, 1); CP_COMMIT();

    for (int c = 0; c < nchunk; c++) {
        CP_WAIT(1);
        __syncthreads();
        if (c + 2 < nchunk) load_chunk(c + 2, (c + 2) % 3);
        CP_COMMIT();

        uint32_t bb = sbase + (c % 3) * BUFB;
        #pragma unroll
        for (int ks = 0; ks < 2; ks++) {
            uint32_t a[2][4], b[2][4];
            #pragma unroll
            for (int mf = 0; mf < 2; mf++)
                ldsm_x4(a[mf], bb + OA + (m0w + mf * 16) * STR + ks * 32 + a_off);
            #pragma unroll
            for (int ng = 0; ng < 2; ng++)
                ldsm_x4(b[ng], bb + OB + (n0w + ng * 16) * STR + ks * 32 + b_off);
            #pragma unroll
            for (int mf = 0; mf < 2; mf++)
                #pragma unroll
                for (int nf = 0; nf < 4; nf++)
                    mma_f16(acc[mf][nf], a[mf], &b[nf >> 1][(nf & 1) * 2]);
        }
    }

    #pragma unroll
    for (int mf = 0; mf < 2; mf++)
        #pragma unroll
        for (int nf = 0; nf < 4; nf++) {
            int col = n0g + n0w + nf * 8 + (lane & 3) * 2;
            float b0 = bias ? bias[col]     : 0.f;
            float b1 = bias ? bias[col + 1] : 0.f;
            int r0 = m0g + m0w + mf * 16 + (lane >> 2);
            float2 v0 = {acc[mf][nf][0] + b0, acc[mf][nf][1] + b1};
            float2 v1 = {acc[mf][nf][2] + b0, acc[mf][nf][3] + b1};
            *(float2*)(C + (size_t)r0 * Nc + col)       = v0;
            *(float2*)(C + (size_t)(r0 + 8) * Nc + col) = v1;
        }
}

// ---------------------------------------------------------------------------
// per-row attention; ctx emitted as fp16 for gemm2
// ---------------------------------------------------------------------------
__global__ void __launch_bounds__(256) attn_kernel(
        const float* __restrict__ qfull,
        const float* __restrict__ Kp, const float* __restrict__ Kn,
        const float* __restrict__ Vp, const float* __restrict__ Vn,
        const int* __restrict__ pos, const int* __restrict__ neg,
        const int* __restrict__ sgn,
        __half* __restrict__ ctxh,
        float* __restrict__ avg_out, float* __restrict__ sel_out,
        int D, float scale) {
    int rn = blockIdx.x;
    int tid = threadIdx.x;
    int warp = tid >> 5, lane = tid & 31;
    __shared__ float qs[D_MAX];
    __shared__ float sc[NHEADS * TKK];

    int sg = sgn[rn];
    const float* Km = sg ? Kp : Kn;
    const float* Vm = sg ? Vp : Vn;
    const int* idx  = sg ? pos : neg;

    for (int j = tid * 4; j < D; j += 1024)
        *(float4*)(qs + j) = *(const float4*)(qfull + (size_t)rn * D + j);
    __syncthreads();

    for (int t = 0; t < 64; t++) {
        int p = warp * 64 + t;
        int h = p >> 5, k = p & 31;
        const float* kr = Km + (size_t)k * D_MAX + h * 64;
        const float* qr = qs + h * 64;
        float v = qr[lane] * kr[lane] + qr[lane + 32] * kr[lane + 32];
        #pragma unroll
        for (int off = 16; off; off >>= 1) v += __shfl_xor_sync(0xffffffffu, v, off);
        if (lane == 0) sc[p] = v * scale;
    }
    __syncthreads();

    #pragma unroll
    for (int hh = warp * 2; hh < warp * 2 + 2; hh++) {
        float v = sc[hh * 32 + lane];
        float mx = v;
        #pragma unroll
        for (int off = 16; off; off >>= 1) mx = fmaxf(mx, __shfl_xor_sync(0xffffffffu, mx, off));
        float e = expf(v - mx);
        float s = e;
        #pragma unroll
        for (int off = 16; off; off >>= 1) s += __shfl_xor_sync(0xffffffffu, s, off);
        sc[hh * 32 + lane] = e / s;
    }
    __syncthreads();

    if (tid < 32) {
        if (avg_out) {
            float a = 0.f;
            #pragma unroll
            for (int h = 0; h < NHEADS; h++) a += sc[h * 32 + tid];
            avg_out[(size_t)rn * TKK + tid] = a * (1.f / NHEADS);
        }
        if (sel_out) sel_out[(size_t)rn * TKK + tid] = (float)idx[tid];
    }

    for (int o = tid; o < D; o += 256) {
        int h = o >> 6;
        const float* arow = sc + h * 32;
        float a = 0.f;
        #pragma unroll
        for (int k = 0; k < TKK; k++) a += arow[k] * Vm[(size_t)k * D_MAX + o];
        ctxh[(size_t)rn * D + o] = __float2half_rn(a);
    }
}

// ---------------------------------------------------------------------------
// LayerNorm in-place per row
// ---------------------------------------------------------------------------
__global__ void __launch_bounds__(256) ln_kernel(
        float* __restrict__ out, const float* __restrict__ gamma,
        const float* __restrict__ beta, int D, float eps) {
    int rn = blockIdx.x;
    float* row = out + (size_t)rn * D;
    int tid = threadIdx.x;
    int warp = tid >> 5, lane = tid & 31;
    __shared__ float ssum[8], ssq[8];

    float s = 0.f, ss = 0.f;
    for (int j = tid * 4; j < D; j += 1024) {
        float4 v = *(const float4*)(row + j);
        s  += v.x + v.y + v.z + v.w;
        ss += v.x * v.x + v.y * v.y + v.z * v.z + v.w * v.w;
    }
    #pragma unroll
    for (int off = 16; off; off >>= 1) {
        s  += __shfl_xor_sync(0xffffffffu, s, off);
        ss += __shfl_xor_sync(0xffffffffu, ss, off);
    }
    if (lane == 0) { ssum[warp] = s; ssq[warp] = ss; }
    __syncthreads();
    if (tid == 0) {
        float ts = 0.f, tq = 0.f;
        #pragma unroll
        for (int w = 0; w < 8; w++) { ts += ssum[w]; tq += ssq[w]; }
        ssum[0] = ts; ssq[0] = tq;
    }
    __syncthreads();
    float mu = ssum[0] / D;
    float var = ssq[0] / D - mu * mu;
    float rstd = rsqrtf(var + eps);
    for (int j = tid * 4; j < D; j += 1024) {
        float4 v = *(const float4*)(row + j);
        float4 g = *(const float4*)(gamma + j);
        float4 bb = *(const float4*)(beta + j);
        v.x = (v.x - mu) * rstd * g.x + bb.x;
        v.y = (v.y - mu) * rstd * g.y + bb.y;
        v.z = (v.z - mu) * rstd * g.z + bb.z;
        v.w = (v.w - mu) * rstd * g.w + bb.w;
        *(float4*)(row + j) = v;
    }
}

// ---------------------------------------------------------------------------
// launch — forked graph (round-15 tail)
// ---------------------------------------------------------------------------
extern "C" void kernel_launch(void* const* d_in, const int* in_sizes, int n_in,
                              void* d_out, int out_size) {
    const float* x     = (const float*)d_in[0];
    const float* mk    = (const float*)d_in[1];
    const float* mv    = (const float*)d_in[2];
    const float* Wq    = (const float*)d_in[3];
    const float* Wk    = (const float*)d_in[4];
    const float* Wv    = (const float*)d_in[5];
    const float* Wo    = (const float*)d_in[6];
    const float* bo    = (const float*)d_in[7];
    const float* gamma = (const float*)d_in[8];
    const float* beta  = (const float*)d_in[9];

    int D    = in_sizes[7];
    int rows = in_sizes[0] / D;           // B*N
    int M    = in_sizes[1] / D;
    int hd   = D / NHEADS;

    float* out = (float*)d_out;
    float* avg_out = nullptr;
    float* sel_out = nullptr;
    if ((long long)out_size >= (long long)rows * (D + 2 * TKK)) {
        avg_out = out + (size_t)rows * D;
        sel_out = avg_out + (size_t)rows * TKK;
    }

    float *p_r, *p_wbar, *p_part, *p_KVk, *p_KVv, *p_qf;
    int *p_pos, *p_neg, *p_sgn;
    unsigned long long* p_cand;
    __half *p_xh, *p_ch, *p_Wqh, *p_Woh, *p_Wkh, *p_Wvh, *p_gk, *p_gv;
    cudaGetSymbolAddress((void**)&p_r,    g_r);
    cudaGetSymbolAddress((void**)&p_wbar, g_wbar);
    cudaGetSymbolAddress((void**)&p_part, g_colpart);
    cudaGetSymbolAddress((void**)&p_pos,  g_posidx);
    cudaGetSymbolAddress((void**)&p_neg,  g_negidx);
    cudaGetSymbolAddress((void**)&p_sgn,  g_sign);
    cudaGetSymbolAddress((void**)&p_cand, g_cand);
    cudaGetSymbolAddress((void**)&p_KVk,  g_KVk);
    cudaGetSymbolAddress((void**)&p_KVv,  g_KVv);
    cudaGetSymbolAddress((void**)&p_qf,   g_qfull);
    cudaGetSymbolAddress((void**)&p_xh,   g_xh);
    cudaGetSymbolAddress((void**)&p_ch,   g_ch);
    cudaGetSymbolAddress((void**)&p_Wqh,  g_Wqh);
    cudaGetSymbolAddress((void**)&p_Woh,  g_Woh);
    cudaGetSymbolAddress((void**)&p_Wkh,  g_Wkh);
    cudaGetSymbolAddress((void**)&p_Wvh,  g_Wvh);
    cudaGetSymbolAddress((void**)&p_gk,   g_gk);
    cudaGetSymbolAddress((void**)&p_gv,   g_gv);

    float* p_Kp = p_KVk;
    float* p_Kn = p_KVk + 32 * D_MAX;
    float* p_Vp = p_KVv;
    float* p_Vn = p_KVv + 32 * D_MAX;

    cudaFuncSetAttribute(gemm_hmma_kernel, cudaFuncAttributeMaxDynamicSharedMemorySize,
                         GEMM_DSMEM);
    cudaFuncSetAttribute(projgemm_kernel, cudaFuncAttributeMaxDynamicSharedMemorySize,
                         PROJ_DSMEM);

    static cudaStream_t sA = nullptr, sB = nullptr;
    static cudaEvent_t e0 = nullptr, eA = nullptr, eB = nullptr, eW = nullptr;
    if (!sA) {
        cudaStreamCreateWithFlags(&sA, cudaStreamNonBlocking);
        cudaStreamCreateWithFlags(&sB, cudaStreamNonBlocking);
        cudaEventCreateWithFlags(&e0, cudaEventDisableTiming);
        cudaEventCreateWithFlags(&eA, cudaEventDisableTiming);
        cudaEventCreateWithFlags(&eB, cudaEventDisableTiming);
        cudaEventCreateWithFlags(&eW, cudaEventDisableTiming);
    }

    float sqrtD = sqrtf((float)D);
    float scale = 1.f / sqrtf((float)hd);
    int nx4 = rows * D / 4, nw4 = D * D / 4;
    int segs = (M + 1023) / 1024;

    // ---- fork ----
    cudaEventRecord(e0, 0);
    cudaStreamWaitEvent(sA, e0, 0);
    cudaStreamWaitEvent(sB, e0, 0);

    // side B front: Wk/Wv/Wo fp16 converts (one batched launch)
    cvtW3_kernel<<<dim3((nw4 + 255) / 256, 3), 256, 0, sB>>>(
        Wk, Wv, Wo, p_Wkh, p_Wvh, p_Woh, nw4);
    cudaEventRecord(eW, sB);

    // side A: rowstat -> topk -> gather -> projgemm
    rowstat_kernel<<<(M + 15) / 16, 256, 0, sA>>>(mk, p_r, M, D, sqrtD);
    topk_stage1<<<dim3(segs, 2), 256, 0, sA>>>(p_r, M, p_cand);
    topk_stage2<<<2, 256, 0, sA>>>(p_cand, segs, p_pos, p_neg);
    cudaStreamWaitEvent(sA, eW, 0);
    gather_kernel<<<dim3(64, 2), 256, 0, sA>>>(mk, mv, p_pos, p_neg, p_gk, p_gv, D);
    projgemm_kernel<<<dim3(D / 128, 2), 256, PROJ_DSMEM, sA>>>(
        p_gk, p_gv, p_Wkh, p_Wvh, p_KVk, p_KVv, D);
    cudaEventRecord(eA, sA);

    // side B rest: colsum -> qmsign
    colsum1_kernel<<<dim3((D + 255) / 256, 32), 256, 0, sB>>>(Wq, p_part, D);
    colsum2_kernel<<<(D + 255) / 256, 256, 0, sB>>>(p_part, p_wbar, D);
    qmsign_kernel<<<(rows + 7) / 8, 256, 0, sB>>>(x, p_wbar, p_sgn, rows, D);
    cudaEventRecord(eB, sB);

    // main: x/Wq converts -> gemm1
    cvt_kernel<<<(nx4 + 255) / 256, 256>>>(x,  p_xh,  nx4);
    cvt_kernel<<<(nw4 + 255) / 256, 256>>>(Wq, p_Wqh, nw4);
    gemm_hmma_kernel<<<dim3(D / 128, rows / 128), 512, GEMM_DSMEM>>>(
        p_xh, p_Wqh, nullptr, p_qf, D, D);

    // ---- join ----
    cudaStreamWaitEvent(0, eA, 0);
    cudaStreamWaitEvent(0, eB, 0);

    attn_kernel<<<rows, 256>>>(p_qf, p_Kp, p_Kn, p_Vp, p_Vn, p_pos, p_neg, p_sgn,
                               p_ch, avg_out, sel_out, D, scale);

    gemm_hmma_kernel<<<dim3(D / 128, rows / 128), 512, GEMM_DSMEM>>>(
        p_ch, p_Woh, bo, out, D, D);

    ln_kernel<<<rows, 256>>>(out, gamma, beta, D, 1e-5f);
}